// round 1
// baseline (speedup 1.0000x reference)
#include <cuda_runtime.h>
#include <math.h>

#define T_TOKENS 8192
#define H_DIM    1024
#define F_DIM    4096
#define E_NUM    8
#define NPAIR    (T_TOKENS * 2)

#define BM 128
#define BN 64
#define BK 16
#define AST 136   // 136 % 32 == 8 -> conflict-free fragment LDS
#define BST 72    // 72 % 32 == 8

// ---------------- scratch (device globals; no runtime allocation) ----------------
__device__ int   g_ke[NPAIR];        // per-token top2 expert ids
__device__ float g_kw[NPAIR];        // per-token top2 softmax weights
__device__ int   g_slot[NPAIR];      // per-(token,j) compact slot
__device__ int   g_off[E_NUM + 1];   // expert offsets into compact slots
__device__ int   g_stok[NPAIR];      // slot -> token
__device__ float g_sw[NPAIR];        // slot -> router weight
__device__ float g_hid[(size_t)NPAIR * F_DIM];   // 268 MB
__device__ float g_dres[(size_t)NPAIR * H_DIM];  // 67 MB

__device__ __forceinline__ unsigned f2tf(float v) {
    unsigned u;
    asm("cvt.rna.tf32.f32 %0, %1;" : "=r"(u) : "f"(v));
    return u;
}

__device__ __forceinline__ void mma_tf32(float* c, const unsigned* a, const unsigned* b) {
    asm volatile(
        "mma.sync.aligned.m16n8k8.row.col.f32.tf32.tf32.f32 "
        "{%0,%1,%2,%3}, {%4,%5,%6,%7}, {%8,%9}, {%0,%1,%2,%3};\n"
        : "+f"(c[0]), "+f"(c[1]), "+f"(c[2]), "+f"(c[3])
        : "r"(a[0]), "r"(a[1]), "r"(a[2]), "r"(a[3]), "r"(b[0]), "r"(b[1]));
}

// ---------------- 1) router: fp32 logits, softmax, top-2 ----------------
__global__ void router_kernel(const float* __restrict__ x, const float* __restrict__ rw) {
    int warp = threadIdx.x >> 5;
    int lane = threadIdx.x & 31;
    int t = blockIdx.x * 8 + warp;
    const float4* xr = (const float4*)(x + (size_t)t * H_DIM);
    float acc[E_NUM];
#pragma unroll
    for (int e = 0; e < E_NUM; e++) acc[e] = 0.f;
#pragma unroll
    for (int it = 0; it < H_DIM / 128; it++) {
        float4 xv = xr[it * 32 + lane];
#pragma unroll
        for (int e = 0; e < E_NUM; e++) {
            float4 wv = ((const float4*)(rw + (size_t)e * H_DIM))[it * 32 + lane];
            acc[e] += xv.x * wv.x + xv.y * wv.y + xv.z * wv.z + xv.w * wv.w;
        }
    }
#pragma unroll
    for (int e = 0; e < E_NUM; e++)
#pragma unroll
        for (int o = 16; o > 0; o >>= 1)
            acc[e] += __shfl_xor_sync(0xffffffffu, acc[e], o);
    if (lane == 0) {
        float mx = acc[0];
#pragma unroll
        for (int e = 1; e < E_NUM; e++) mx = fmaxf(mx, acc[e]);
        float p[E_NUM], s = 0.f;
#pragma unroll
        for (int e = 0; e < E_NUM; e++) { p[e] = expf(acc[e] - mx); s += p[e]; }
        float inv = 1.f / s;
        int i1 = 0;
#pragma unroll
        for (int e = 1; e < E_NUM; e++) if (acc[e] > acc[i1]) i1 = e;
        int i2 = (i1 == 0) ? 1 : 0;
#pragma unroll
        for (int e = 0; e < E_NUM; e++) {
            if (e == i1) continue;
            if (acc[e] > acc[i2]) i2 = e;
        }
        g_ke[t * 2]     = i1;  g_kw[t * 2]     = p[i1] * inv;
        g_ke[t * 2 + 1] = i2;  g_kw[t * 2 + 1] = p[i2] * inv;
    }
}

// ---------------- 2) build compact expert buckets ----------------
__global__ void build_kernel() {
    __shared__ int cnt[E_NUM], fill[E_NUM], off_s[E_NUM + 1];
    if (threadIdx.x < E_NUM) { cnt[threadIdx.x] = 0; fill[threadIdx.x] = 0; }
    __syncthreads();
    for (int i = threadIdx.x; i < NPAIR; i += blockDim.x)
        atomicAdd(&cnt[g_ke[i]], 1);
    __syncthreads();
    if (threadIdx.x == 0) {
        int s = 0;
        for (int e = 0; e < E_NUM; e++) { off_s[e] = s; s += cnt[e]; }
        off_s[E_NUM] = s;
        for (int e = 0; e <= E_NUM; e++) g_off[e] = off_s[e];
    }
    __syncthreads();
    for (int i = threadIdx.x; i < NPAIR; i += blockDim.x) {
        int e = g_ke[i];
        int pos = off_s[e] + atomicAdd(&fill[e], 1);
        g_slot[i] = pos;
        g_stok[pos] = i >> 1;
        g_sw[pos] = g_kw[i];
    }
}

// ---------------- 3) fused gate+up GEMM + silu + weight scale ----------------
__global__ __launch_bounds__(256) void gateup_kernel(
    const float* __restrict__ x,
    const float* __restrict__ gw,
    const float* __restrict__ uw)
{
    const int e = blockIdx.z;
    const int off0 = g_off[e];
    const int nrows = g_off[e + 1] - off0;
    const int m0 = blockIdx.y * BM;
    if (m0 >= nrows) return;
    const int n0 = blockIdx.x * BN;

    __shared__ unsigned As[2][BK][AST];
    __shared__ unsigned Bg[2][BK][BST];
    __shared__ unsigned Bu[2][BK][BST];
    __shared__ float ws[BM];

    const int tid = threadIdx.x;
    const int lane = tid & 31, warp = tid >> 5;
    const int warpM = warp & 3, warpN = warp >> 2;
    const int gid = lane >> 2, tig = lane & 3;

    if (tid < BM) {
        int r = m0 + tid;
        ws[tid] = (r < nrows) ? g_sw[off0 + r] : 0.f;
    }

    const int arow = tid >> 2;       // 0..63
    const int kg   = (tid & 3) * 4;  // k sub-group

    const float* ap[2];
#pragma unroll
    for (int p = 0; p < 2; p++) {
        int r = m0 + arow + p * 64;
        if (r > nrows - 1) r = nrows - 1;   // clamp: safe load, store masked later
        int tok = g_stok[off0 + r];
        ap[p] = x + (size_t)tok * H_DIM + kg;
    }
    const float* gp = gw + (size_t)e * F_DIM * H_DIM + (size_t)(n0 + arow) * H_DIM + kg;
    const float* up = uw + (size_t)e * F_DIM * H_DIM + (size_t)(n0 + arow) * H_DIM + kg;

    float accg[2][4][4], accu[2][4][4];
#pragma unroll
    for (int mt = 0; mt < 2; mt++)
#pragma unroll
        for (int nt = 0; nt < 4; nt++)
#pragma unroll
            for (int i = 0; i < 4; i++) { accg[mt][nt][i] = 0.f; accu[mt][nt][i] = 0.f; }

    float4 ra0 = *(const float4*)(ap[0]);
    float4 ra1 = *(const float4*)(ap[1]);
    float4 rbg = *(const float4*)(gp);
    float4 rbu = *(const float4*)(up);
    {
        float va[4], vb[4], vg[4], vu[4];
        *(float4*)va = ra0; *(float4*)vb = ra1; *(float4*)vg = rbg; *(float4*)vu = rbu;
#pragma unroll
        for (int j = 0; j < 4; j++) {
            As[0][kg + j][arow]      = f2tf(va[j]);
            As[0][kg + j][arow + 64] = f2tf(vb[j]);
            Bg[0][kg + j][arow]      = f2tf(vg[j]);
            Bu[0][kg + j][arow]      = f2tf(vu[j]);
        }
    }
    __syncthreads();

    const int nk = H_DIM / BK;  // 64
    for (int kb = 0; kb < nk; kb++) {
        const int st = kb & 1;
        if (kb + 1 < nk) {
            int ko = (kb + 1) * BK;
            ra0 = *(const float4*)(ap[0] + ko);
            ra1 = *(const float4*)(ap[1] + ko);
            rbg = *(const float4*)(gp + ko);
            rbu = *(const float4*)(up + ko);
        }
#pragma unroll
        for (int kk = 0; kk < 2; kk++) {
            const int kb8 = kk * 8;
            unsigned af[2][4], bgf[4][2], buf[4][2];
#pragma unroll
            for (int mt = 0; mt < 2; mt++) {
                int mr = warpM * 32 + mt * 16 + gid;
                af[mt][0] = As[st][kb8 + tig][mr];
                af[mt][1] = As[st][kb8 + tig][mr + 8];
                af[mt][2] = As[st][kb8 + tig + 4][mr];
                af[mt][3] = As[st][kb8 + tig + 4][mr + 8];
            }
#pragma unroll
            for (int nt = 0; nt < 4; nt++) {
                int nc = warpN * 32 + nt * 8 + gid;
                bgf[nt][0] = Bg[st][kb8 + tig][nc];
                bgf[nt][1] = Bg[st][kb8 + tig + 4][nc];
                buf[nt][0] = Bu[st][kb8 + tig][nc];
                buf[nt][1] = Bu[st][kb8 + tig + 4][nc];
            }
#pragma unroll
            for (int mt = 0; mt < 2; mt++)
#pragma unroll
                for (int nt = 0; nt < 4; nt++) {
                    mma_tf32(accg[mt][nt], af[mt], bgf[nt]);
                    mma_tf32(accu[mt][nt], af[mt], buf[nt]);
                }
        }
        if (kb + 1 < nk) {
            const int s2 = st ^ 1;
            float va[4], vb[4], vg[4], vu[4];
            *(float4*)va = ra0; *(float4*)vb = ra1; *(float4*)vg = rbg; *(float4*)vu = rbu;
#pragma unroll
            for (int j = 0; j < 4; j++) {
                As[s2][kg + j][arow]      = f2tf(va[j]);
                As[s2][kg + j][arow + 64] = f2tf(vb[j]);
                Bg[s2][kg + j][arow]      = f2tf(vg[j]);
                Bu[s2][kg + j][arow]      = f2tf(vu[j]);
            }
        }
        __syncthreads();
    }

    // epilogue: hid = w * silu(g) * u
#pragma unroll
    for (int mt = 0; mt < 2; mt++) {
#pragma unroll
        for (int nt = 0; nt < 4; nt++) {
            int cb = n0 + warpN * 32 + nt * 8 + tig * 2;
#pragma unroll
            for (int h = 0; h < 2; h++) {
                int row = warpM * 32 + mt * 16 + gid + h * 8;
                if (m0 + row < nrows) {
                    float w  = ws[row];
                    float g0 = accg[mt][nt][h * 2 + 0], g1 = accg[mt][nt][h * 2 + 1];
                    float u0 = accu[mt][nt][h * 2 + 0], u1 = accu[mt][nt][h * 2 + 1];
                    float h0 = w * u0 * (g0 / (1.f + expf(-g0)));
                    float h1 = w * u1 * (g1 / (1.f + expf(-g1)));
                    size_t base = (size_t)(off0 + m0 + row) * F_DIM + cb;
                    *(float2*)(g_hid + base) = make_float2(h0, h1);
                }
            }
        }
    }
}

// ---------------- 4) down GEMM (per-slot output) ----------------
__global__ __launch_bounds__(256) void down_kernel(const float* __restrict__ dw)
{
    const int e = blockIdx.z;
    const int off0 = g_off[e];
    const int nrows = g_off[e + 1] - off0;
    const int m0 = blockIdx.y * BM;
    if (m0 >= nrows) return;
    const int n0 = blockIdx.x * BN;

    __shared__ unsigned As[2][BK][AST];
    __shared__ unsigned Bs[2][BK][BST];

    const int tid = threadIdx.x;
    const int lane = tid & 31, warp = tid >> 5;
    const int warpM = warp & 3, warpN = warp >> 2;
    const int gid = lane >> 2, tig = lane & 3;

    const int arow = tid >> 2;
    const int kg   = (tid & 3) * 4;

    const float* ap[2];
#pragma unroll
    for (int p = 0; p < 2; p++) {
        int r = m0 + arow + p * 64;
        if (r > nrows - 1) r = nrows - 1;
        ap[p] = g_hid + (size_t)(off0 + r) * F_DIM + kg;
    }
    const float* bp = dw + (size_t)e * H_DIM * F_DIM + (size_t)(n0 + arow) * F_DIM + kg;

    float acc[2][4][4];
#pragma unroll
    for (int mt = 0; mt < 2; mt++)
#pragma unroll
        for (int nt = 0; nt < 4; nt++)
#pragma unroll
            for (int i = 0; i < 4; i++) acc[mt][nt][i] = 0.f;

    float4 ra0 = *(const float4*)(ap[0]);
    float4 ra1 = *(const float4*)(ap[1]);
    float4 rb  = *(const float4*)(bp);
    {
        float va[4], vb[4], vc[4];
        *(float4*)va = ra0; *(float4*)vb = ra1; *(float4*)vc = rb;
#pragma unroll
        for (int j = 0; j < 4; j++) {
            As[0][kg + j][arow]      = f2tf(va[j]);
            As[0][kg + j][arow + 64] = f2tf(vb[j]);
            Bs[0][kg + j][arow]      = f2tf(vc[j]);
        }
    }
    __syncthreads();

    const int nk = F_DIM / BK;  // 256
    for (int kb = 0; kb < nk; kb++) {
        const int st = kb & 1;
        if (kb + 1 < nk) {
            int ko = (kb + 1) * BK;
            ra0 = *(const float4*)(ap[0] + ko);
            ra1 = *(const float4*)(ap[1] + ko);
            rb  = *(const float4*)(bp + ko);
        }
#pragma unroll
        for (int kk = 0; kk < 2; kk++) {
            const int kb8 = kk * 8;
            unsigned af[2][4], bf[4][2];
#pragma unroll
            for (int mt = 0; mt < 2; mt++) {
                int mr = warpM * 32 + mt * 16 + gid;
                af[mt][0] = As[st][kb8 + tig][mr];
                af[mt][1] = As[st][kb8 + tig][mr + 8];
                af[mt][2] = As[st][kb8 + tig + 4][mr];
                af[mt][3] = As[st][kb8 + tig + 4][mr + 8];
            }
#pragma unroll
            for (int nt = 0; nt < 4; nt++) {
                int nc = warpN * 32 + nt * 8 + gid;
                bf[nt][0] = Bs[st][kb8 + tig][nc];
                bf[nt][1] = Bs[st][kb8 + tig + 4][nc];
            }
#pragma unroll
            for (int mt = 0; mt < 2; mt++)
#pragma unroll
                for (int nt = 0; nt < 4; nt++)
                    mma_tf32(acc[mt][nt], af[mt], bf[nt]);
        }
        if (kb + 1 < nk) {
            const int s2 = st ^ 1;
            float va[4], vb[4], vc[4];
            *(float4*)va = ra0; *(float4*)vb = ra1; *(float4*)vc = rb;
#pragma unroll
            for (int j = 0; j < 4; j++) {
                As[s2][kg + j][arow]      = f2tf(va[j]);
                As[s2][kg + j][arow + 64] = f2tf(vb[j]);
                Bs[s2][kg + j][arow]      = f2tf(vc[j]);
            }
        }
        __syncthreads();
    }

#pragma unroll
    for (int mt = 0; mt < 2; mt++) {
#pragma unroll
        for (int nt = 0; nt < 4; nt++) {
            int cb = n0 + warpN * 32 + nt * 8 + tig * 2;
#pragma unroll
            for (int h = 0; h < 2; h++) {
                int row = warpM * 32 + mt * 16 + gid + h * 8;
                if (m0 + row < nrows) {
                    size_t base = (size_t)(off0 + m0 + row) * H_DIM + cb;
                    *(float2*)(g_dres + base) =
                        make_float2(acc[mt][nt][h * 2 + 0], acc[mt][nt][h * 2 + 1]);
                }
            }
        }
    }
}

// ---------------- 5) combine: out[t] = dres[slot0] + dres[slot1] ----------------
__global__ void combine_kernel(float* __restrict__ out) {
    int t = blockIdx.x;
    int s0 = g_slot[2 * t], s1 = g_slot[2 * t + 1];
    const float4* p0 = (const float4*)(g_dres + (size_t)s0 * H_DIM);
    const float4* p1 = (const float4*)(g_dres + (size_t)s1 * H_DIM);
    float4* po = (float4*)(out + (size_t)t * H_DIM);
    int i = threadIdx.x;
    float4 a = p0[i], b = p1[i];
    po[i] = make_float4(a.x + b.x, a.y + b.y, a.z + b.z, a.w + b.w);
}

// ---------------- launch ----------------
extern "C" void kernel_launch(void* const* d_in, const int* in_sizes, int n_in,
                              void* d_out, int out_size) {
    (void)in_sizes; (void)n_in; (void)out_size;
    const float* x  = (const float*)d_in[0];
    const float* rw = (const float*)d_in[1];
    const float* gw = (const float*)d_in[2];
    const float* uw = (const float*)d_in[3];
    const float* dw = (const float*)d_in[4];
    float* out = (float*)d_out;

    router_kernel<<<T_TOKENS / 8, 256>>>(x, rw);
    build_kernel<<<1, 256>>>();
    gateup_kernel<<<dim3(F_DIM / BN, T_TOKENS / BM, E_NUM), 256>>>(x, gw, uw);
    down_kernel<<<dim3(H_DIM / BN, T_TOKENS / BM, E_NUM), 256>>>(dw);
    combine_kernel<<<T_TOKENS, 256>>>(out);
}

// round 3
// speedup vs baseline: 1.5850x; 1.5850x over previous
#include <cuda_runtime.h>
#include <cstdint>
#include <math.h>

#define T_TOKENS 8192
#define H_DIM    1024
#define F_DIM    4096
#define E_NUM    8
#define NPAIR    (T_TOKENS * 2)
#define WEL      (E_NUM * F_DIM * H_DIM)   // elements per weight tensor (gate/up/down)

// ---------------- scratch (device globals) ----------------
__device__ int   g_ke[NPAIR];
__device__ float g_kw[NPAIR];
__device__ int   g_slot[NPAIR];
__device__ int   g_off[E_NUM + 1];
__device__ int   g_stok[NPAIR];
__device__ float g_sw[NPAIR];
__device__ float g_ax[(size_t)NPAIR * H_DIM];    // gathered + tf32-rounded A (67 MB)
__device__ float g_hid[(size_t)NPAIR * F_DIM];   // 268 MB (stored tf32-rounded)
__device__ float g_dres[(size_t)NPAIR * H_DIM];  // 67 MB
__device__ float g_gwr[WEL];                     // 134 MB rounded gate_w
__device__ float g_uwr[WEL];                     // 134 MB rounded up_w
__device__ float g_dwr[WEL];                     // 134 MB rounded down_w

// ---------------- helpers ----------------
__device__ __forceinline__ unsigned f2tf(float v) {
    unsigned u; asm("cvt.rna.tf32.f32 %0, %1;" : "=r"(u) : "f"(v)); return u;
}
__device__ __forceinline__ uint32_t smem_u32(const void* p) {
    uint32_t a;
    asm("{ .reg .u64 t; cvta.to.shared.u64 t, %1; cvt.u32.u64 %0, t; }" : "=r"(a) : "l"(p));
    return a;
}
__device__ __forceinline__ void mma_tf32(float* c, const unsigned* a, const unsigned* b) {
    asm volatile(
        "mma.sync.aligned.m16n8k8.row.col.f32.tf32.tf32.f32 "
        "{%0,%1,%2,%3}, {%4,%5,%6,%7}, {%8,%9}, {%0,%1,%2,%3};\n"
        : "+f"(c[0]), "+f"(c[1]), "+f"(c[2]), "+f"(c[3])
        : "r"(a[0]), "r"(a[1]), "r"(a[2]), "r"(a[3]), "r"(b[0]), "r"(b[1]));
}
__device__ __forceinline__ void cp16(uint32_t dst, const void* src) {
    asm volatile("cp.async.cg.shared.global [%0], [%1], 16;" :: "r"(dst), "l"(src) : "memory");
}
#define CP_COMMIT() asm volatile("cp.async.commit_group;" ::: "memory")
#define CP_WAIT0()  asm volatile("cp.async.wait_group 0;" ::: "memory")
#define CP_WAIT1()  asm volatile("cp.async.wait_group 1;" ::: "memory")

#define PADW 36        // padded row stride in words (32 data + 4 pad)
#define STG_WORDS 9216 // one pipeline stage in floats (36864 B)

// ---------------- 0) prep: round weights to tf32 ----------------
__global__ void round_kernel(const float4* __restrict__ src, float4* __restrict__ dst, int n4) {
    int i = blockIdx.x * blockDim.x + threadIdx.x;
    int stride = gridDim.x * blockDim.x;
    for (; i < n4; i += stride) {
        float4 v = src[i];
        uint4 u;
        u.x = f2tf(v.x); u.y = f2tf(v.y); u.z = f2tf(v.z); u.w = f2tf(v.w);
        ((uint4*)dst)[i] = u;
    }
}

// ---------------- 1) router ----------------
__global__ void router_kernel(const float* __restrict__ x, const float* __restrict__ rw) {
    int warp = threadIdx.x >> 5;
    int lane = threadIdx.x & 31;
    int t = blockIdx.x * 8 + warp;
    const float4* xr = (const float4*)(x + (size_t)t * H_DIM);
    float acc[E_NUM];
#pragma unroll
    for (int e = 0; e < E_NUM; e++) acc[e] = 0.f;
#pragma unroll
    for (int it = 0; it < H_DIM / 128; it++) {
        float4 xv = xr[it * 32 + lane];
#pragma unroll
        for (int e = 0; e < E_NUM; e++) {
            float4 wv = ((const float4*)(rw + (size_t)e * H_DIM))[it * 32 + lane];
            acc[e] += xv.x * wv.x + xv.y * wv.y + xv.z * wv.z + xv.w * wv.w;
        }
    }
#pragma unroll
    for (int e = 0; e < E_NUM; e++)
#pragma unroll
        for (int o = 16; o > 0; o >>= 1)
            acc[e] += __shfl_xor_sync(0xffffffffu, acc[e], o);
    if (lane == 0) {
        float mx = acc[0];
#pragma unroll
        for (int e = 1; e < E_NUM; e++) mx = fmaxf(mx, acc[e]);
        float p[E_NUM], s = 0.f;
#pragma unroll
        for (int e = 0; e < E_NUM; e++) { p[e] = expf(acc[e] - mx); s += p[e]; }
        float inv = 1.f / s;
        int i1 = 0;
#pragma unroll
        for (int e = 1; e < E_NUM; e++) if (acc[e] > acc[i1]) i1 = e;
        int i2 = (i1 == 0) ? 1 : 0;
#pragma unroll
        for (int e = 0; e < E_NUM; e++) {
            if (e == i1) continue;
            if (acc[e] > acc[i2]) i2 = e;
        }
        g_ke[t * 2]     = i1;  g_kw[t * 2]     = p[i1] * inv;
        g_ke[t * 2 + 1] = i2;  g_kw[t * 2 + 1] = p[i2] * inv;
    }
}

// ---------------- 2) build buckets ----------------
__global__ void build_kernel() {
    __shared__ int cnt[E_NUM], fill[E_NUM], off_s[E_NUM + 1];
    if (threadIdx.x < E_NUM) { cnt[threadIdx.x] = 0; fill[threadIdx.x] = 0; }
    __syncthreads();
    for (int i = threadIdx.x; i < NPAIR; i += blockDim.x)
        atomicAdd(&cnt[g_ke[i]], 1);
    __syncthreads();
    if (threadIdx.x == 0) {
        int s = 0;
        for (int e = 0; e < E_NUM; e++) { off_s[e] = s; s += cnt[e]; }
        off_s[E_NUM] = s;
        for (int e = 0; e <= E_NUM; e++) g_off[e] = off_s[e];
    }
    __syncthreads();
    for (int i = threadIdx.x; i < NPAIR; i += blockDim.x) {
        int e = g_ke[i];
        int pos = off_s[e] + atomicAdd(&fill[e], 1);
        g_slot[i] = pos;
        g_stok[pos] = i >> 1;
        g_sw[pos] = g_kw[i];
    }
}

// ---------------- 2b) gather + round A ----------------
__global__ void gather_x_kernel(const float* __restrict__ x) {
    int s = blockIdx.x;
    int tok = g_stok[s];
    float4 v = ((const float4*)(x + (size_t)tok * H_DIM))[threadIdx.x];
    uint4 u;
    u.x = f2tf(v.x); u.y = f2tf(v.y); u.z = f2tf(v.z); u.w = f2tf(v.w);
    ((uint4*)(g_ax + (size_t)s * H_DIM))[threadIdx.x] = u;
}

// ---------------- 3) gate+up GEMM ----------------
// BM=128, BN=64 (each for gate and up), BK=32, 2-stage cp.async pipeline.
// stage layout (floats): A[128*36] @0 | Bg[64*36] @4608 | Bu[64*36] @6912
#define GU_SMEM (2 * STG_WORDS * 4)
__global__ __launch_bounds__(256, 2)
void gateup_mm(const float* __restrict__ gw, const float* __restrict__ uw)
{
    const int e = blockIdx.z;
    const int off0 = g_off[e];
    const int nrows = g_off[e + 1] - off0;
    const int m0 = blockIdx.y * 128;
    if (m0 >= nrows) return;
    const int n0 = blockIdx.x * 64;
    const int tid = threadIdx.x;
    const int wid = tid >> 5, lane = tid & 31;
    const int warpM = wid & 3, warpN = wid >> 2;   // 4 x 2
    const int g = lane >> 2, t = lane & 3;

    extern __shared__ float sm[];
    __shared__ float ws[128];
    const uint32_t sbase = smem_u32(sm);

    if (tid < 128) {
        int r = m0 + tid;
        ws[tid] = (r < nrows) ? g_sw[off0 + r] : 0.f;
    }

    // cp.async source/dest setup
    const float* aSrc[4]; uint32_t aDst[4];
#pragma unroll
    for (int i = 0; i < 4; i++) {
        int c = tid + 256 * i;          // 1024 chunks: 128 rows x 8 cols
        int row = c >> 3, col = c & 7;
        int r = m0 + row; if (r > nrows - 1) r = nrows - 1;
        aSrc[i] = g_ax + (size_t)(off0 + r) * H_DIM + col * 4;
        aDst[i] = sbase + (row * PADW + col * 4) * 4;
    }
    const float* gSrc[2]; const float* uSrc[2]; uint32_t bDst[2];
#pragma unroll
    for (int i = 0; i < 2; i++) {
        int c = tid + 256 * i;          // 512 chunks: 64 rows x 8 cols
        int row = c >> 3, col = c & 7;
        gSrc[i] = gw + (size_t)e * F_DIM * H_DIM + (size_t)(n0 + row) * H_DIM + col * 4;
        uSrc[i] = uw + (size_t)e * F_DIM * H_DIM + (size_t)(n0 + row) * H_DIM + col * 4;
        bDst[i] = sbase + (row * PADW + col * 4) * 4;
    }

    float accg[2][4][4], accu[2][4][4];
#pragma unroll
    for (int mt = 0; mt < 2; mt++)
#pragma unroll
        for (int nt = 0; nt < 4; nt++)
#pragma unroll
            for (int i = 0; i < 4; i++) { accg[mt][nt][i] = 0.f; accu[mt][nt][i] = 0.f; }

    // prologue: stage 0, kb 0
#pragma unroll
    for (int i = 0; i < 4; i++) cp16(aDst[i], aSrc[i]);
#pragma unroll
    for (int i = 0; i < 2; i++) cp16(bDst[i] + 4608 * 4, gSrc[i]);
#pragma unroll
    for (int i = 0; i < 2; i++) cp16(bDst[i] + 6912 * 4, uSrc[i]);
    CP_COMMIT();

    const int NK = H_DIM / 32;  // 32
    for (int kb = 0; kb < NK; kb++) {
        const int s = kb & 1;
        if (kb + 1 < NK) {
            const uint32_t so = (uint32_t)((s ^ 1) * STG_WORDS * 4);
            const int ko = (kb + 1) * 32;
#pragma unroll
            for (int i = 0; i < 4; i++) cp16(aDst[i] + so, aSrc[i] + ko);
#pragma unroll
            for (int i = 0; i < 2; i++) cp16(bDst[i] + so + 4608 * 4, gSrc[i] + ko);
#pragma unroll
            for (int i = 0; i < 2; i++) cp16(bDst[i] + so + 6912 * 4, uSrc[i] + ko);
            CP_COMMIT();
            CP_WAIT1();
        } else {
            CP_WAIT0();
        }
        __syncthreads();
        const float* sA = sm + s * STG_WORDS;
        const float* sG = sA + 4608;
        const float* sU = sA + 6912;
#pragma unroll
        for (int ks = 0; ks < 4; ks++) {
            const int k8 = ks * 8;
            unsigned a[2][4], bg[4][2], bu[4][2];
#pragma unroll
            for (int mt = 0; mt < 2; mt++) {
                const float* p = sA + (warpM * 32 + mt * 16 + g) * PADW + k8 + t;
                a[mt][0] = __float_as_uint(p[0]);
                a[mt][1] = __float_as_uint(p[8 * PADW]);
                a[mt][2] = __float_as_uint(p[4]);
                a[mt][3] = __float_as_uint(p[8 * PADW + 4]);
            }
#pragma unroll
            for (int nt = 0; nt < 4; nt++) {
                const float* pg = sG + (warpN * 32 + nt * 8 + g) * PADW + k8 + t;
                const float* pu = sU + (warpN * 32 + nt * 8 + g) * PADW + k8 + t;
                bg[nt][0] = __float_as_uint(pg[0]); bg[nt][1] = __float_as_uint(pg[4]);
                bu[nt][0] = __float_as_uint(pu[0]); bu[nt][1] = __float_as_uint(pu[4]);
            }
#pragma unroll
            for (int mt = 0; mt < 2; mt++)
#pragma unroll
                for (int nt = 0; nt < 4; nt++) {
                    mma_tf32(accg[mt][nt], a[mt], bg[nt]);
                    mma_tf32(accu[mt][nt], a[mt], bu[nt]);
                }
        }
        __syncthreads();
    }

    // epilogue: hid = round_tf32( w * silu(g) * u )
#pragma unroll
    for (int mt = 0; mt < 2; mt++) {
#pragma unroll
        for (int nt = 0; nt < 4; nt++) {
            const int col = n0 + warpN * 32 + nt * 8 + t * 2;
#pragma unroll
            for (int h = 0; h < 2; h++) {
                const int row = warpM * 32 + mt * 16 + g + h * 8;
                if (m0 + row < nrows) {
                    float w  = ws[row];
                    float g0 = accg[mt][nt][h * 2 + 0], g1 = accg[mt][nt][h * 2 + 1];
                    float u0 = accu[mt][nt][h * 2 + 0], u1 = accu[mt][nt][h * 2 + 1];
                    float h0 = w * u0 * (g0 / (1.f + __expf(-g0)));
                    float h1 = w * u1 * (g1 / (1.f + __expf(-g1)));
                    uint2 o = make_uint2(f2tf(h0), f2tf(h1));
                    *(uint2*)(g_hid + (size_t)(off0 + m0 + row) * F_DIM + col) = o;
                }
            }
        }
    }
}

// ---------------- 4) down GEMM ----------------
// BM=128, BN=128, BK=32; warp tile 32x64 (4x2 warps).
// stage layout: A[128*36] @0 | B[128*36] @4608
#define DN_SMEM (2 * STG_WORDS * 4)
__global__ __launch_bounds__(256, 2)
void down_mm(void)
{
    const int e = blockIdx.z;
    const int off0 = g_off[e];
    const int nrows = g_off[e + 1] - off0;
    const int m0 = blockIdx.y * 128;
    if (m0 >= nrows) return;
    const int n0 = blockIdx.x * 128;
    const int tid = threadIdx.x;
    const int wid = tid >> 5, lane = tid & 31;
    const int warpM = wid & 3, warpN = wid >> 2;   // 4 x 2
    const int g = lane >> 2, t = lane & 3;

    extern __shared__ float sm[];
    const uint32_t sbase = smem_u32(sm);

    const float* aSrc[4]; uint32_t aDst[4];
    const float* bSrc[4]; uint32_t bDst[4];
#pragma unroll
    for (int i = 0; i < 4; i++) {
        int c = tid + 256 * i;
        int row = c >> 3, col = c & 7;
        int r = m0 + row; if (r > nrows - 1) r = nrows - 1;
        aSrc[i] = g_hid + (size_t)(off0 + r) * F_DIM + col * 4;
        aDst[i] = sbase + (row * PADW + col * 4) * 4;
        bSrc[i] = g_dwr + (size_t)e * H_DIM * F_DIM + (size_t)(n0 + row) * F_DIM + col * 4;
        bDst[i] = sbase + ((4608 + row * PADW + col * 4)) * 4;
    }

    float acc[2][8][4];
#pragma unroll
    for (int mt = 0; mt < 2; mt++)
#pragma unroll
        for (int nt = 0; nt < 8; nt++)
#pragma unroll
            for (int i = 0; i < 4; i++) acc[mt][nt][i] = 0.f;

#pragma unroll
    for (int i = 0; i < 4; i++) { cp16(aDst[i], aSrc[i]); cp16(bDst[i], bSrc[i]); }
    CP_COMMIT();

    const int NK = F_DIM / 32;  // 128
    for (int kb = 0; kb < NK; kb++) {
        const int s = kb & 1;
        if (kb + 1 < NK) {
            const uint32_t so = (uint32_t)((s ^ 1) * STG_WORDS * 4);
            const int ko = (kb + 1) * 32;
#pragma unroll
            for (int i = 0; i < 4; i++) {
                cp16(aDst[i] + so, aSrc[i] + ko);
                cp16(bDst[i] + so, bSrc[i] + ko);
            }
            CP_COMMIT();
            CP_WAIT1();
        } else {
            CP_WAIT0();
        }
        __syncthreads();
        const float* sA = sm + s * STG_WORDS;
        const float* sB = sA + 4608;
#pragma unroll
        for (int ks = 0; ks < 4; ks++) {
            const int k8 = ks * 8;
            unsigned a[2][4], b[8][2];
#pragma unroll
            for (int mt = 0; mt < 2; mt++) {
                const float* p = sA + (warpM * 32 + mt * 16 + g) * PADW + k8 + t;
                a[mt][0] = __float_as_uint(p[0]);
                a[mt][1] = __float_as_uint(p[8 * PADW]);
                a[mt][2] = __float_as_uint(p[4]);
                a[mt][3] = __float_as_uint(p[8 * PADW + 4]);
            }
#pragma unroll
            for (int nt = 0; nt < 8; nt++) {
                const float* p = sB + (warpN * 64 + nt * 8 + g) * PADW + k8 + t;
                b[nt][0] = __float_as_uint(p[0]);
                b[nt][1] = __float_as_uint(p[4]);
            }
#pragma unroll
            for (int mt = 0; mt < 2; mt++)
#pragma unroll
                for (int nt = 0; nt < 8; nt++)
                    mma_tf32(acc[mt][nt], a[mt], b[nt]);
        }
        __syncthreads();
    }

#pragma unroll
    for (int mt = 0; mt < 2; mt++) {
#pragma unroll
        for (int nt = 0; nt < 8; nt++) {
            const int col = n0 + warpN * 64 + nt * 8 + t * 2;
#pragma unroll
            for (int h = 0; h < 2; h++) {
                const int row = warpM * 32 + mt * 16 + g + h * 8;
                if (m0 + row < nrows) {
                    *(float2*)(g_dres + (size_t)(off0 + m0 + row) * H_DIM + col) =
                        make_float2(acc[mt][nt][h * 2 + 0], acc[mt][nt][h * 2 + 1]);
                }
            }
        }
    }
}

// ---------------- 5) combine ----------------
__global__ void combine_kernel(float* __restrict__ out) {
    int tt = blockIdx.x;
    int s0 = g_slot[2 * tt], s1 = g_slot[2 * tt + 1];
    const float4* p0 = (const float4*)(g_dres + (size_t)s0 * H_DIM);
    const float4* p1 = (const float4*)(g_dres + (size_t)s1 * H_DIM);
    float4* po = (float4*)(out + (size_t)tt * H_DIM);
    int i = threadIdx.x;
    float4 a = p0[i], b = p1[i];
    po[i] = make_float4(a.x + b.x, a.y + b.y, a.z + b.z, a.w + b.w);
}

// ---------------- launch ----------------
extern "C" void kernel_launch(void* const* d_in, const int* in_sizes, int n_in,
                              void* d_out, int out_size) {
    (void)in_sizes; (void)n_in; (void)out_size;
    const float* x  = (const float*)d_in[0];
    const float* rw = (const float*)d_in[1];
    const float* gw = (const float*)d_in[2];
    const float* uw = (const float*)d_in[3];
    const float* dw = (const float*)d_in[4];
    float* out = (float*)d_out;

    cudaFuncSetAttribute(gateup_mm, cudaFuncAttributeMaxDynamicSharedMemorySize, GU_SMEM);
    cudaFuncSetAttribute(down_mm,   cudaFuncAttributeMaxDynamicSharedMemorySize, DN_SMEM);

    float* gwr; float* uwr; float* dwr;
    cudaGetSymbolAddress((void**)&gwr, g_gwr);
    cudaGetSymbolAddress((void**)&uwr, g_uwr);
    cudaGetSymbolAddress((void**)&dwr, g_dwr);

    const int n4 = WEL / 4;
    round_kernel<<<4096, 256>>>((const float4*)gw, (float4*)gwr, n4);
    round_kernel<<<4096, 256>>>((const float4*)uw, (float4*)uwr, n4);
    round_kernel<<<4096, 256>>>((const float4*)dw, (float4*)dwr, n4);

    router_kernel<<<T_TOKENS / 8, 256>>>(x, rw);
    build_kernel<<<1, 256>>>();
    gather_x_kernel<<<NPAIR, 256>>>(x);

    gateup_mm<<<dim3(F_DIM / 64, NPAIR / 128, E_NUM), 256, GU_SMEM>>>(gwr, uwr);
    down_mm<<<dim3(H_DIM / 128, NPAIR / 128, E_NUM), 256, DN_SMEM>>>();
    combine_kernel<<<T_TOKENS, 256>>>(out);
}

// round 4
// speedup vs baseline: 1.5879x; 1.0018x over previous
#include <cuda_runtime.h>
#include <cstdint>
#include <math.h>

#define T_TOKENS 8192
#define H_DIM    1024
#define F_DIM    4096
#define E_NUM    8
#define NPAIR    (T_TOKENS * 2)
#define WEL      (E_NUM * F_DIM * H_DIM)

// ---------------- scratch (device globals) ----------------
__device__ int   g_ke[NPAIR];
__device__ float g_kw[NPAIR];
__device__ int   g_slot[NPAIR];
__device__ int   g_off[E_NUM + 1];
__device__ int   g_stok[NPAIR];
__device__ float g_sw[NPAIR];
__device__ float g_ax[(size_t)NPAIR * H_DIM];    // gathered + rounded + K-permuted A
__device__ float g_hid[(size_t)NPAIR * F_DIM];   // rounded + K-permuted hidden
__device__ float g_dres[(size_t)NPAIR * H_DIM];
__device__ float g_gwr[WEL];                     // rounded + K-permuted weights
__device__ float g_uwr[WEL];
__device__ float g_dwr[WEL];

// ---------------- helpers ----------------
__device__ __forceinline__ unsigned f2tf(float v) {
    unsigned u; asm("cvt.rna.tf32.f32 %0, %1;" : "=r"(u) : "f"(v)); return u;
}
__device__ __forceinline__ uint32_t smem_u32(const void* p) {
    uint32_t a;
    asm("{ .reg .u64 t; cvta.to.shared.u64 t, %1; cvt.u32.u64 %0, t; }" : "=r"(a) : "l"(p));
    return a;
}
__device__ __forceinline__ void mma_tf32(float* c, const unsigned* a, const unsigned* b) {
    asm volatile(
        "mma.sync.aligned.m16n8k8.row.col.f32.tf32.tf32.f32 "
        "{%0,%1,%2,%3}, {%4,%5,%6,%7}, {%8,%9}, {%0,%1,%2,%3};\n"
        : "+f"(c[0]), "+f"(c[1]), "+f"(c[2]), "+f"(c[3])
        : "r"(a[0]), "r"(a[1]), "r"(a[2]), "r"(a[3]), "r"(b[0]), "r"(b[1]));
}
__device__ __forceinline__ void cp16(uint32_t dst, const void* src) {
    asm volatile("cp.async.cg.shared.global [%0], [%1], 16;" :: "r"(dst), "l"(src) : "memory");
}
#define CP_COMMIT() asm volatile("cp.async.commit_group;" ::: "memory")
#define CP_WAIT0()  asm volatile("cp.async.wait_group 0;" ::: "memory")
#define CP_WAIT1()  asm volatile("cp.async.wait_group 1;" ::: "memory")

#define PADW 40            // padded row stride in words -> conflict-free LDS.64
#define GU_STG (128*PADW + 64*PADW + 64*PADW)   // 10240 words / stage
#define DN_STG (128*PADW + 128*PADW)            // 10240 words / stage
#define GU_SMEM (2 * GU_STG * 4)
#define DN_SMEM (2 * DN_STG * 4)

// K-permutation within each 8-group: logical q -> pos 2*(q&3) + (q>>2)
// so memory order is [0,4,1,5,2,6,3,7]; pair (t, t+4) is contiguous (LDS.64).

// ---------------- 0) prep: round + permute weights ----------------
// grid.y selects tensor (0=gate,1=up,2=down); flat float4 index i:
// group base word = 8*(i>>1), parity = i&1 -> positions base + parity + {0,2,4,6}
__global__ void round_perm_kernel(const float4* __restrict__ s0,
                                  const float4* __restrict__ s1,
                                  const float4* __restrict__ s2,
                                  float* __restrict__ d0,
                                  float* __restrict__ d1,
                                  float* __restrict__ d2, int n4) {
    const float4* src = (blockIdx.y == 0) ? s0 : (blockIdx.y == 1) ? s1 : s2;
    float* dst = (blockIdx.y == 0) ? d0 : (blockIdx.y == 1) ? d1 : d2;
    int i = blockIdx.x * blockDim.x + threadIdx.x;
    int stride = gridDim.x * blockDim.x;
    for (; i < n4; i += stride) {
        float4 v = src[i];
        size_t base = (size_t)(i >> 1) * 8 + (i & 1);
        dst[base + 0] = __uint_as_float(f2tf(v.x));
        dst[base + 2] = __uint_as_float(f2tf(v.y));
        dst[base + 4] = __uint_as_float(f2tf(v.z));
        dst[base + 6] = __uint_as_float(f2tf(v.w));
    }
}

// ---------------- 1) router ----------------
__global__ void router_kernel(const float* __restrict__ x, const float* __restrict__ rw) {
    int warp = threadIdx.x >> 5;
    int lane = threadIdx.x & 31;
    int t = blockIdx.x * 8 + warp;
    const float4* xr = (const float4*)(x + (size_t)t * H_DIM);
    float acc[E_NUM];
#pragma unroll
    for (int e = 0; e < E_NUM; e++) acc[e] = 0.f;
#pragma unroll
    for (int it = 0; it < H_DIM / 128; it++) {
        float4 xv = xr[it * 32 + lane];
#pragma unroll
        for (int e = 0; e < E_NUM; e++) {
            float4 wv = ((const float4*)(rw + (size_t)e * H_DIM))[it * 32 + lane];
            acc[e] += xv.x * wv.x + xv.y * wv.y + xv.z * wv.z + xv.w * wv.w;
        }
    }
#pragma unroll
    for (int e = 0; e < E_NUM; e++)
#pragma unroll
        for (int o = 16; o > 0; o >>= 1)
            acc[e] += __shfl_xor_sync(0xffffffffu, acc[e], o);
    if (lane == 0) {
        float mx = acc[0];
#pragma unroll
        for (int e = 1; e < E_NUM; e++) mx = fmaxf(mx, acc[e]);
        float p[E_NUM], s = 0.f;
#pragma unroll
        for (int e = 0; e < E_NUM; e++) { p[e] = expf(acc[e] - mx); s += p[e]; }
        float inv = 1.f / s;
        int i1 = 0;
#pragma unroll
        for (int e = 1; e < E_NUM; e++) if (acc[e] > acc[i1]) i1 = e;
        int i2 = (i1 == 0) ? 1 : 0;
#pragma unroll
        for (int e = 0; e < E_NUM; e++) {
            if (e == i1) continue;
            if (acc[e] > acc[i2]) i2 = e;
        }
        g_ke[t * 2]     = i1;  g_kw[t * 2]     = p[i1] * inv;
        g_ke[t * 2 + 1] = i2;  g_kw[t * 2 + 1] = p[i2] * inv;
    }
}

// ---------------- 2) build buckets ----------------
__global__ void build_kernel() {
    __shared__ int cnt[E_NUM], fill[E_NUM], off_s[E_NUM + 1];
    if (threadIdx.x < E_NUM) { cnt[threadIdx.x] = 0; fill[threadIdx.x] = 0; }
    __syncthreads();
    for (int i = threadIdx.x; i < NPAIR; i += blockDim.x)
        atomicAdd(&cnt[g_ke[i]], 1);
    __syncthreads();
    if (threadIdx.x == 0) {
        int s = 0;
        for (int e = 0; e < E_NUM; e++) { off_s[e] = s; s += cnt[e]; }
        off_s[E_NUM] = s;
        for (int e = 0; e <= E_NUM; e++) g_off[e] = off_s[e];
    }
    __syncthreads();
    for (int i = threadIdx.x; i < NPAIR; i += blockDim.x) {
        int e = g_ke[i];
        int pos = off_s[e] + atomicAdd(&fill[e], 1);
        g_slot[i] = pos;
        g_stok[pos] = i >> 1;
        g_sw[pos] = g_kw[i];
    }
}

// ---------------- 2b) gather + round + permute A ----------------
__global__ void gather_x_kernel(const float* __restrict__ x) {
    int s = blockIdx.x;
    int tok = g_stok[s];
    int i = threadIdx.x;   // float4 index over H_DIM/4 = 256
    float4 v = ((const float4*)(x + (size_t)tok * H_DIM))[i];
    float* dst = g_ax + (size_t)s * H_DIM + (i >> 1) * 8 + (i & 1);
    dst[0] = __uint_as_float(f2tf(v.x));
    dst[2] = __uint_as_float(f2tf(v.y));
    dst[4] = __uint_as_float(f2tf(v.z));
    dst[6] = __uint_as_float(f2tf(v.w));
}

// ---------------- 3) gate+up GEMM ----------------
// BM=128, BN=64 per matrix, BK=32, 2-stage cp.async, K-permuted LDS.64 fragments.
// stage layout (words): A[128*40]@0 | Bg[64*40]@5120 | Bu[64*40]@7680
__global__ __launch_bounds__(256, 2)
void gateup_mm(const float* __restrict__ gw, const float* __restrict__ uw)
{
    const int e = blockIdx.z;
    const int off0 = g_off[e];
    const int nrows = g_off[e + 1] - off0;
    const int m0 = blockIdx.y * 128;
    if (m0 >= nrows) return;
    const int n0 = blockIdx.x * 64;
    const int tid = threadIdx.x;
    const int wid = tid >> 5, lane = tid & 31;
    const int warpM = wid & 3, warpN = wid >> 2;
    const int g = lane >> 2, t = lane & 3;

    extern __shared__ float sm[];
    __shared__ float ws[128];
    const uint32_t sbase = smem_u32(sm);

    if (tid < 128) {
        int r = m0 + tid;
        ws[tid] = (r < nrows) ? g_sw[off0 + r] : 0.f;
    }

    const float* aSrc[4]; uint32_t aDst[4];
#pragma unroll
    for (int i = 0; i < 4; i++) {
        int c = tid + 256 * i;
        int row = c >> 3, col = c & 7;
        int r = m0 + row; if (r > nrows - 1) r = nrows - 1;
        aSrc[i] = g_ax + (size_t)(off0 + r) * H_DIM + col * 4;
        aDst[i] = sbase + (row * PADW + col * 4) * 4;
    }
    const float* gSrc[2]; const float* uSrc[2]; uint32_t bDst[2];
#pragma unroll
    for (int i = 0; i < 2; i++) {
        int c = tid + 256 * i;
        int row = c >> 3, col = c & 7;
        gSrc[i] = gw + (size_t)e * F_DIM * H_DIM + (size_t)(n0 + row) * H_DIM + col * 4;
        uSrc[i] = uw + (size_t)e * F_DIM * H_DIM + (size_t)(n0 + row) * H_DIM + col * 4;
        bDst[i] = sbase + (row * PADW + col * 4) * 4;
    }

    float accg[2][4][4], accu[2][4][4];
#pragma unroll
    for (int mt = 0; mt < 2; mt++)
#pragma unroll
        for (int nt = 0; nt < 4; nt++)
#pragma unroll
            for (int i = 0; i < 4; i++) { accg[mt][nt][i] = 0.f; accu[mt][nt][i] = 0.f; }

#pragma unroll
    for (int i = 0; i < 4; i++) cp16(aDst[i], aSrc[i]);
#pragma unroll
    for (int i = 0; i < 2; i++) cp16(bDst[i] + 5120 * 4, gSrc[i]);
#pragma unroll
    for (int i = 0; i < 2; i++) cp16(bDst[i] + 7680 * 4, uSrc[i]);
    CP_COMMIT();

    const int NK = H_DIM / 32;
    for (int kb = 0; kb < NK; kb++) {
        const int s = kb & 1;
        if (kb + 1 < NK) {
            const uint32_t so = (uint32_t)((s ^ 1) * GU_STG * 4);
            const int ko = (kb + 1) * 32;
#pragma unroll
            for (int i = 0; i < 4; i++) cp16(aDst[i] + so, aSrc[i] + ko);
#pragma unroll
            for (int i = 0; i < 2; i++) cp16(bDst[i] + so + 5120 * 4, gSrc[i] + ko);
#pragma unroll
            for (int i = 0; i < 2; i++) cp16(bDst[i] + so + 7680 * 4, uSrc[i] + ko);
            CP_COMMIT();
            CP_WAIT1();
        } else {
            CP_WAIT0();
        }
        __syncthreads();
        const float* sA = sm + s * GU_STG;
        const float* sG = sA + 5120;
        const float* sU = sA + 7680;
#pragma unroll
        for (int ks = 0; ks < 4; ks++) {
            const int k8 = ks * 8 + 2 * t;
            unsigned a[2][4], bg[4][2], bu[4][2];
#pragma unroll
            for (int mt = 0; mt < 2; mt++) {
                const int r0 = warpM * 32 + mt * 16 + g;
                float2 v0 = *(const float2*)(sA + r0 * PADW + k8);
                float2 v1 = *(const float2*)(sA + (r0 + 8) * PADW + k8);
                a[mt][0] = __float_as_uint(v0.x); a[mt][2] = __float_as_uint(v0.y);
                a[mt][1] = __float_as_uint(v1.x); a[mt][3] = __float_as_uint(v1.y);
            }
#pragma unroll
            for (int nt = 0; nt < 4; nt++) {
                const int rn = warpN * 32 + nt * 8 + g;
                float2 vg = *(const float2*)(sG + rn * PADW + k8);
                float2 vu = *(const float2*)(sU + rn * PADW + k8);
                bg[nt][0] = __float_as_uint(vg.x); bg[nt][1] = __float_as_uint(vg.y);
                bu[nt][0] = __float_as_uint(vu.x); bu[nt][1] = __float_as_uint(vu.y);
            }
#pragma unroll
            for (int mt = 0; mt < 2; mt++)
#pragma unroll
                for (int nt = 0; nt < 4; nt++) {
                    mma_tf32(accg[mt][nt], a[mt], bg[nt]);
                    mma_tf32(accu[mt][nt], a[mt], bu[nt]);
                }
        }
        __syncthreads();
    }

    // epilogue: hid = round_tf32( w * silu(g) * u ), stored K-PERMUTED for down
    const int p0 = (t < 2) ? 4 * t : 4 * t - 7;   // pos of logical q=2t within 8-group
#pragma unroll
    for (int mt = 0; mt < 2; mt++) {
#pragma unroll
        for (int nt = 0; nt < 4; nt++) {
            const int gbase = n0 + warpN * 32 + nt * 8;
#pragma unroll
            for (int h = 0; h < 2; h++) {
                const int row = warpM * 32 + mt * 16 + g + h * 8;
                if (m0 + row < nrows) {
                    float w  = ws[row];
                    float g0 = accg[mt][nt][h * 2 + 0], g1 = accg[mt][nt][h * 2 + 1];
                    float u0 = accu[mt][nt][h * 2 + 0], u1 = accu[mt][nt][h * 2 + 1];
                    float h0 = w * u0 * (g0 / (1.f + __expf(-g0)));
                    float h1 = w * u1 * (g1 / (1.f + __expf(-g1)));
                    float* d = g_hid + (size_t)(off0 + m0 + row) * F_DIM + gbase;
                    d[p0]     = __uint_as_float(f2tf(h0));
                    d[p0 + 2] = __uint_as_float(f2tf(h1));
                }
            }
        }
    }
}

// ---------------- 4) down GEMM ----------------
// BM=128, BN=128, BK=32; warp tile 32x64. stage: A[128*40]@0 | B[128*40]@5120
__global__ __launch_bounds__(256, 2)
void down_mm(void)
{
    const int e = blockIdx.z;
    const int off0 = g_off[e];
    const int nrows = g_off[e + 1] - off0;
    const int m0 = blockIdx.y * 128;
    if (m0 >= nrows) return;
    const int n0 = blockIdx.x * 128;
    const int tid = threadIdx.x;
    const int wid = tid >> 5, lane = tid & 31;
    const int warpM = wid & 3, warpN = wid >> 2;
    const int g = lane >> 2, t = lane & 3;

    extern __shared__ float sm[];
    const uint32_t sbase = smem_u32(sm);

    const float* aSrc[4]; uint32_t aDst[4];
    const float* bSrc[4]; uint32_t bDst[4];
#pragma unroll
    for (int i = 0; i < 4; i++) {
        int c = tid + 256 * i;
        int row = c >> 3, col = c & 7;
        int r = m0 + row; if (r > nrows - 1) r = nrows - 1;
        aSrc[i] = g_hid + (size_t)(off0 + r) * F_DIM + col * 4;
        aDst[i] = sbase + (row * PADW + col * 4) * 4;
        bSrc[i] = g_dwr + (size_t)e * H_DIM * F_DIM + (size_t)(n0 + row) * F_DIM + col * 4;
        bDst[i] = sbase + ((5120 + row * PADW + col * 4)) * 4;
    }

    float acc[2][8][4];
#pragma unroll
    for (int mt = 0; mt < 2; mt++)
#pragma unroll
        for (int nt = 0; nt < 8; nt++)
#pragma unroll
            for (int i = 0; i < 4; i++) acc[mt][nt][i] = 0.f;

#pragma unroll
    for (int i = 0; i < 4; i++) { cp16(aDst[i], aSrc[i]); cp16(bDst[i], bSrc[i]); }
    CP_COMMIT();

    const int NK = F_DIM / 32;
    for (int kb = 0; kb < NK; kb++) {
        const int s = kb & 1;
        if (kb + 1 < NK) {
            const uint32_t so = (uint32_t)((s ^ 1) * DN_STG * 4);
            const int ko = (kb + 1) * 32;
#pragma unroll
            for (int i = 0; i < 4; i++) {
                cp16(aDst[i] + so, aSrc[i] + ko);
                cp16(bDst[i] + so, bSrc[i] + ko);
            }
            CP_COMMIT();
            CP_WAIT1();
        } else {
            CP_WAIT0();
        }
        __syncthreads();
        const float* sA = sm + s * DN_STG;
        const float* sB = sA + 5120;
#pragma unroll
        for (int ks = 0; ks < 4; ks++) {
            const int k8 = ks * 8 + 2 * t;
            unsigned a[2][4], b[8][2];
#pragma unroll
            for (int mt = 0; mt < 2; mt++) {
                const int r0 = warpM * 32 + mt * 16 + g;
                float2 v0 = *(const float2*)(sA + r0 * PADW + k8);
                float2 v1 = *(const float2*)(sA + (r0 + 8) * PADW + k8);
                a[mt][0] = __float_as_uint(v0.x); a[mt][2] = __float_as_uint(v0.y);
                a[mt][1] = __float_as_uint(v1.x); a[mt][3] = __float_as_uint(v1.y);
            }
#pragma unroll
            for (int nt = 0; nt < 8; nt++) {
                const int rn = warpN * 64 + nt * 8 + g;
                float2 vb = *(const float2*)(sB + rn * PADW + k8);
                b[nt][0] = __float_as_uint(vb.x); b[nt][1] = __float_as_uint(vb.y);
            }
#pragma unroll
            for (int mt = 0; mt < 2; mt++)
#pragma unroll
                for (int nt = 0; nt < 8; nt++)
                    mma_tf32(acc[mt][nt], a[mt], b[nt]);
        }
        __syncthreads();
    }

#pragma unroll
    for (int mt = 0; mt < 2; mt++) {
#pragma unroll
        for (int nt = 0; nt < 8; nt++) {
            const int col = n0 + warpN * 64 + nt * 8 + t * 2;
#pragma unroll
            for (int h = 0; h < 2; h++) {
                const int row = warpM * 32 + mt * 16 + g + h * 8;
                if (m0 + row < nrows) {
                    *(float2*)(g_dres + (size_t)(off0 + m0 + row) * H_DIM + col) =
                        make_float2(acc[mt][nt][h * 2 + 0], acc[mt][nt][h * 2 + 1]);
                }
            }
        }
    }
}

// ---------------- 5) combine ----------------
__global__ void combine_kernel(float* __restrict__ out) {
    int tt = blockIdx.x;
    int s0 = g_slot[2 * tt], s1 = g_slot[2 * tt + 1];
    const float4* p0 = (const float4*)(g_dres + (size_t)s0 * H_DIM);
    const float4* p1 = (const float4*)(g_dres + (size_t)s1 * H_DIM);
    float4* po = (float4*)(out + (size_t)tt * H_DIM);
    int i = threadIdx.x;
    float4 a = p0[i], b = p1[i];
    po[i] = make_float4(a.x + b.x, a.y + b.y, a.z + b.z, a.w + b.w);
}

// ---------------- launch ----------------
extern "C" void kernel_launch(void* const* d_in, const int* in_sizes, int n_in,
                              void* d_out, int out_size) {
    (void)in_sizes; (void)n_in; (void)out_size;
    const float* x  = (const float*)d_in[0];
    const float* rw = (const float*)d_in[1];
    const float* gw = (const float*)d_in[2];
    const float* uw = (const float*)d_in[3];
    const float* dw = (const float*)d_in[4];
    float* out = (float*)d_out;

    cudaFuncSetAttribute(gateup_mm, cudaFuncAttributeMaxDynamicSharedMemorySize, GU_SMEM);
    cudaFuncSetAttribute(down_mm,   cudaFuncAttributeMaxDynamicSharedMemorySize, DN_SMEM);

    float* gwr; float* uwr; float* dwr;
    cudaGetSymbolAddress((void**)&gwr, g_gwr);
    cudaGetSymbolAddress((void**)&uwr, g_uwr);
    cudaGetSymbolAddress((void**)&dwr, g_dwr);

    const int n4 = WEL / 4;
    round_perm_kernel<<<dim3(2048, 3), 256>>>((const float4*)gw, (const float4*)uw,
                                              (const float4*)dw, gwr, uwr, dwr, n4);

    router_kernel<<<T_TOKENS / 8, 256>>>(x, rw);
    build_kernel<<<1, 256>>>();
    gather_x_kernel<<<NPAIR, 256>>>(x);

    gateup_mm<<<dim3(F_DIM / 64, NPAIR / 128, E_NUM), 256, GU_SMEM>>>(gwr, uwr);
    down_mm<<<dim3(H_DIM / 128, NPAIR / 128, E_NUM), 256, DN_SMEM>>>();
    combine_kernel<<<T_TOKENS, 256>>>(out);
}

// round 6
// speedup vs baseline: 2.8519x; 1.7960x over previous
#include <cuda_runtime.h>
#include <cuda_fp16.h>
#include <cstdint>
#include <math.h>

#define T_TOKENS 8192
#define H_DIM    1024
#define F_DIM    4096
#define E_NUM    8
#define NPAIR    (T_TOKENS * 2)
#define WEL      (E_NUM * F_DIM * H_DIM)

// ---------------- scratch (device globals) ----------------
__device__ int    g_ke[NPAIR];
__device__ float  g_kw[NPAIR];
__device__ int    g_slot[NPAIR];
__device__ int    g_off[E_NUM + 1];
__device__ int    g_stok[NPAIR];
__device__ float  g_sw[NPAIR];
__device__ __half g_axh[(size_t)NPAIR * H_DIM];   // gathered + fp16 + K-permuted A
__device__ __half g_hidh[(size_t)NPAIR * F_DIM];  // fp16 + K-permuted hidden
__device__ float  g_dres[(size_t)NPAIR * H_DIM];
__device__ __half g_gwh[WEL];                     // fp16 + K-permuted weights
__device__ __half g_uwh[WEL];
__device__ __half g_dwh[WEL];

// K-permutation within each 16-group: logical j -> pos 4*((j>>1)&3) + 2*(j>>3) + (j&1)
// memory order: [0,1,8,9, 2,3,10,11, 4,5,12,13, 6,7,14,15]
// => fragment halves (2t,2t+1,2t+8,2t+9) are 4 contiguous halves (one LDS.64).

// ---------------- helpers ----------------
__device__ __forceinline__ uint32_t smem_u32(const void* p) {
    uint32_t a;
    asm("{ .reg .u64 t; cvta.to.shared.u64 t, %1; cvt.u32.u64 %0, t; }" : "=r"(a) : "l"(p));
    return a;
}
__device__ __forceinline__ void mma_f16(float* c, const unsigned* a, const unsigned* b) {
    asm volatile(
        "mma.sync.aligned.m16n8k16.row.col.f32.f16.f16.f32 "
        "{%0,%1,%2,%3}, {%4,%5,%6,%7}, {%8,%9}, {%0,%1,%2,%3};\n"
        : "+f"(c[0]), "+f"(c[1]), "+f"(c[2]), "+f"(c[3])
        : "r"(a[0]), "r"(a[1]), "r"(a[2]), "r"(a[3]), "r"(b[0]), "r"(b[1]));
}
__device__ __forceinline__ void cp16(uint32_t dst, const void* src) {
    asm volatile("cp.async.cg.shared.global [%0], [%1], 16;" :: "r"(dst), "l"(src) : "memory");
}
#define CP_COMMIT() asm volatile("cp.async.commit_group;" ::: "memory")
#define CP_WAIT0()  asm volatile("cp.async.wait_group 0;" ::: "memory")
#define CP_WAIT1()  asm volatile("cp.async.wait_group 1;" ::: "memory")

#define PADH 80                       // padded row stride in halves (160 B)
#define GU_STGH (128*PADH + 64*PADH + 64*PADH)  // 20480 halves / stage
#define DN_STGH (128*PADH + 128*PADH)           // 20480 halves / stage
#define GU_SMEM (2 * GU_STGH * 2)
#define DN_SMEM (2 * DN_STGH * 2)

// ---------------- 0) prep: fp16 + permute weights ----------------
__global__ void round_perm_kernel(const float* __restrict__ s0,
                                  const float* __restrict__ s1,
                                  const float* __restrict__ s2,
                                  __half* __restrict__ d0,
                                  __half* __restrict__ d1,
                                  __half* __restrict__ d2, int n16) {
    const float* src = (blockIdx.y == 0) ? s0 : (blockIdx.y == 1) ? s1 : s2;
    __half* dst = (blockIdx.y == 0) ? d0 : (blockIdx.y == 1) ? d1 : d2;
    int i = blockIdx.x * blockDim.x + threadIdx.x;
    int stride = gridDim.x * blockDim.x;
    for (; i < n16; i += stride) {
        const float4* s = (const float4*)(src + (size_t)i * 16);
        float4 v0 = s[0], v1 = s[1], v2 = s[2], v3 = s[3];
        float in[16] = {v0.x, v0.y, v0.z, v0.w, v1.x, v1.y, v1.z, v1.w,
                        v2.x, v2.y, v2.z, v2.w, v3.x, v3.y, v3.z, v3.w};
        __half o[16];
#pragma unroll
        for (int j = 0; j < 16; j++) {
            int p = 4 * ((j >> 1) & 3) + 2 * (j >> 3) + (j & 1);
            o[p] = __float2half_rn(in[j]);
        }
        uint4* d = (uint4*)(dst + (size_t)i * 16);   // 16 halves = 32 B = 2x uint4
        d[0] = ((const uint4*)o)[0];
        d[1] = ((const uint4*)o)[1];
    }
}

// ---------------- 1) router ----------------
__global__ void router_kernel(const float* __restrict__ x, const float* __restrict__ rw) {
    int warp = threadIdx.x >> 5;
    int lane = threadIdx.x & 31;
    int t = blockIdx.x * 8 + warp;
    const float4* xr = (const float4*)(x + (size_t)t * H_DIM);
    float acc[E_NUM];
#pragma unroll
    for (int e = 0; e < E_NUM; e++) acc[e] = 0.f;
#pragma unroll
    for (int it = 0; it < H_DIM / 128; it++) {
        float4 xv = xr[it * 32 + lane];
#pragma unroll
        for (int e = 0; e < E_NUM; e++) {
            float4 wv = ((const float4*)(rw + (size_t)e * H_DIM))[it * 32 + lane];
            acc[e] += xv.x * wv.x + xv.y * wv.y + xv.z * wv.z + xv.w * wv.w;
        }
    }
#pragma unroll
    for (int e = 0; e < E_NUM; e++)
#pragma unroll
        for (int o = 16; o > 0; o >>= 1)
            acc[e] += __shfl_xor_sync(0xffffffffu, acc[e], o);
    if (lane == 0) {
        float mx = acc[0];
#pragma unroll
        for (int e = 1; e < E_NUM; e++) mx = fmaxf(mx, acc[e]);
        float p[E_NUM], s = 0.f;
#pragma unroll
        for (int e = 0; e < E_NUM; e++) { p[e] = expf(acc[e] - mx); s += p[e]; }
        float inv = 1.f / s;
        int i1 = 0;
#pragma unroll
        for (int e = 1; e < E_NUM; e++) if (acc[e] > acc[i1]) i1 = e;
        int i2 = (i1 == 0) ? 1 : 0;
#pragma unroll
        for (int e = 0; e < E_NUM; e++) {
            if (e == i1) continue;
            if (acc[e] > acc[i2]) i2 = e;
        }
        g_ke[t * 2]     = i1;  g_kw[t * 2]     = p[i1] * inv;
        g_ke[t * 2 + 1] = i2;  g_kw[t * 2 + 1] = p[i2] * inv;
    }
}

// ---------------- 2) build buckets ----------------
__global__ void build_kernel() {
    __shared__ int cnt[E_NUM], fill[E_NUM], off_s[E_NUM + 1];
    if (threadIdx.x < E_NUM) { cnt[threadIdx.x] = 0; fill[threadIdx.x] = 0; }
    __syncthreads();
    for (int i = threadIdx.x; i < NPAIR; i += blockDim.x)
        atomicAdd(&cnt[g_ke[i]], 1);
    __syncthreads();
    if (threadIdx.x == 0) {
        int s = 0;
        for (int e = 0; e < E_NUM; e++) { off_s[e] = s; s += cnt[e]; }
        off_s[E_NUM] = s;
        for (int e = 0; e <= E_NUM; e++) g_off[e] = off_s[e];
    }
    __syncthreads();
    for (int i = threadIdx.x; i < NPAIR; i += blockDim.x) {
        int e = g_ke[i];
        int pos = off_s[e] + atomicAdd(&fill[e], 1);
        g_slot[i] = pos;
        g_stok[pos] = i >> 1;
        g_sw[pos] = g_kw[i];
    }
}

// ---------------- 2b) gather + fp16 + permute A ----------------
// block: 256 threads = 4 rows x 64 groups of 16
__global__ void gather_x_kernel(const float* __restrict__ x) {
    int row = blockIdx.x * 4 + (threadIdx.x >> 6);
    int grp = threadIdx.x & 63;
    int tok = g_stok[row];
    const float4* s = (const float4*)(x + (size_t)tok * H_DIM + grp * 16);
    float4 v0 = s[0], v1 = s[1], v2 = s[2], v3 = s[3];
    float in[16] = {v0.x, v0.y, v0.z, v0.w, v1.x, v1.y, v1.z, v1.w,
                    v2.x, v2.y, v2.z, v2.w, v3.x, v3.y, v3.z, v3.w};
    __half o[16];
#pragma unroll
    for (int j = 0; j < 16; j++) {
        int p = 4 * ((j >> 1) & 3) + 2 * (j >> 3) + (j & 1);
        o[p] = __float2half_rn(in[j]);
    }
    uint4* d = (uint4*)(g_axh + (size_t)row * H_DIM + grp * 16);  // 32 B
    d[0] = ((const uint4*)o)[0];
    d[1] = ((const uint4*)o)[1];
}

// ---------------- 3) gate+up GEMM (fp16 mma) ----------------
// BM=128, BN=64 per matrix, BK=64, 2-stage cp.async.
// stage (halves): A[128*80]@0 | Bg[64*80]@10240 | Bu[64*80]@15360
__global__ __launch_bounds__(256, 2)
void gateup_mm(const __half* __restrict__ gw, const __half* __restrict__ uw)
{
    const int e = blockIdx.z;
    const int off0 = g_off[e];
    const int nrows = g_off[e + 1] - off0;
    const int m0 = blockIdx.y * 128;
    if (m0 >= nrows) return;
    const int n0 = blockIdx.x * 64;
    const int tid = threadIdx.x;
    const int wid = tid >> 5, lane = tid & 31;
    const int warpM = wid & 3, warpN = wid >> 2;
    const int g = lane >> 2, t = lane & 3;

    extern __shared__ __half smh[];
    __shared__ float ws[128];
    const uint32_t sbase = smem_u32(smh);

    if (tid < 128) {
        int r = m0 + tid;
        ws[tid] = (r < nrows) ? g_sw[off0 + r] : 0.f;
    }

    // fill: A 1024 chunks (4/thread), Bg 512 (2/thread), Bu 512 (2/thread)
    const __half* aSrc[4]; uint32_t aDst[4];
#pragma unroll
    for (int i = 0; i < 4; i++) {
        int c = tid + 256 * i;
        int row = c >> 3, col = c & 7;
        int r = m0 + row; if (r > nrows - 1) r = nrows - 1;
        aSrc[i] = g_axh + (size_t)(off0 + r) * H_DIM + col * 8;
        aDst[i] = sbase + (row * PADH + col * 8) * 2;
    }
    const __half* gSrc[2]; const __half* uSrc[2]; uint32_t bDst[2];
#pragma unroll
    for (int i = 0; i < 2; i++) {
        int c = tid + 256 * i;
        int row = c >> 3, col = c & 7;
        gSrc[i] = gw + (size_t)e * F_DIM * H_DIM + (size_t)(n0 + row) * H_DIM + col * 8;
        uSrc[i] = uw + (size_t)e * F_DIM * H_DIM + (size_t)(n0 + row) * H_DIM + col * 8;
        bDst[i] = sbase + (row * PADH + col * 8) * 2;
    }

    float accg[2][4][4], accu[2][4][4];
#pragma unroll
    for (int mt = 0; mt < 2; mt++)
#pragma unroll
        for (int nt = 0; nt < 4; nt++)
#pragma unroll
            for (int i = 0; i < 4; i++) { accg[mt][nt][i] = 0.f; accu[mt][nt][i] = 0.f; }

#pragma unroll
    for (int i = 0; i < 4; i++) cp16(aDst[i], aSrc[i]);
#pragma unroll
    for (int i = 0; i < 2; i++) cp16(bDst[i] + 10240 * 2, gSrc[i]);
#pragma unroll
    for (int i = 0; i < 2; i++) cp16(bDst[i] + 15360 * 2, uSrc[i]);
    CP_COMMIT();

    const int NK = H_DIM / 64;  // 16
    for (int kb = 0; kb < NK; kb++) {
        const int s = kb & 1;
        if (kb + 1 < NK) {
            const uint32_t so = (uint32_t)((s ^ 1) * GU_STGH * 2);
            const int ko = (kb + 1) * 64;
#pragma unroll
            for (int i = 0; i < 4; i++) cp16(aDst[i] + so, aSrc[i] + ko);
#pragma unroll
            for (int i = 0; i < 2; i++) cp16(bDst[i] + so + 10240 * 2, gSrc[i] + ko);
#pragma unroll
            for (int i = 0; i < 2; i++) cp16(bDst[i] + so + 15360 * 2, uSrc[i] + ko);
            CP_COMMIT();
            CP_WAIT1();
        } else {
            CP_WAIT0();
        }
        __syncthreads();
        const __half* sA = smh + s * GU_STGH;
        const __half* sG = sA + 10240;
        const __half* sU = sA + 15360;
#pragma unroll
        for (int ks = 0; ks < 4; ks++) {
            const int k0 = ks * 16 + 4 * t;
            unsigned a[2][4], bg[4][2], bu[4][2];
#pragma unroll
            for (int mt = 0; mt < 2; mt++) {
                const int r0 = warpM * 32 + mt * 16 + g;
                uint2 v0 = *(const uint2*)(sA + r0 * PADH + k0);
                uint2 v1 = *(const uint2*)(sA + (r0 + 8) * PADH + k0);
                a[mt][0] = v0.x; a[mt][2] = v0.y;
                a[mt][1] = v1.x; a[mt][3] = v1.y;
            }
#pragma unroll
            for (int nt = 0; nt < 4; nt++) {
                const int rn = warpN * 32 + nt * 8 + g;
                uint2 vg = *(const uint2*)(sG + rn * PADH + k0);
                uint2 vu = *(const uint2*)(sU + rn * PADH + k0);
                bg[nt][0] = vg.x; bg[nt][1] = vg.y;
                bu[nt][0] = vu.x; bu[nt][1] = vu.y;
            }
#pragma unroll
            for (int mt = 0; mt < 2; mt++)
#pragma unroll
                for (int nt = 0; nt < 4; nt++) {
                    mma_f16(accg[mt][nt], a[mt], bg[nt]);
                    mma_f16(accu[mt][nt], a[mt], bu[nt]);
                }
        }
        __syncthreads();
    }

    // epilogue: hid = fp16( w * silu(g) * u ), stored K-PERMUTED for down GEMM
#pragma unroll
    for (int mt = 0; mt < 2; mt++) {
#pragma unroll
        for (int nt = 0; nt < 4; nt++) {
            const int c = n0 + warpN * 32 + nt * 8 + t * 2;   // logical col of h0
            const int j = c & 15;
            const int p = 4 * ((j >> 1) & 3) + 2 * (j >> 3);
            const int cdst = (c & ~15) + p;
#pragma unroll
            for (int h = 0; h < 2; h++) {
                const int row = warpM * 32 + mt * 16 + g + h * 8;
                if (m0 + row < nrows) {
                    float w  = ws[row];
                    float g0 = accg[mt][nt][h * 2 + 0], g1 = accg[mt][nt][h * 2 + 1];
                    float u0 = accu[mt][nt][h * 2 + 0], u1 = accu[mt][nt][h * 2 + 1];
                    float h0 = w * u0 * (g0 / (1.f + __expf(-g0)));
                    float h1 = w * u1 * (g1 / (1.f + __expf(-g1)));
                    *(__half2*)(g_hidh + (size_t)(off0 + m0 + row) * F_DIM + cdst) =
                        __floats2half2_rn(h0, h1);
                }
            }
        }
    }
}

// ---------------- 4) down GEMM (fp16 mma) ----------------
// BM=128, BN=128, BK=64; warp tile 32x64. stage: A[128*80]@0 | B[128*80]@10240
__global__ __launch_bounds__(256, 2)
void down_mm(void)
{
    const int e = blockIdx.z;
    const int off0 = g_off[e];
    const int nrows = g_off[e + 1] - off0;
    const int m0 = blockIdx.y * 128;
    if (m0 >= nrows) return;
    const int n0 = blockIdx.x * 128;
    const int tid = threadIdx.x;
    const int wid = tid >> 5, lane = tid & 31;
    const int warpM = wid & 3, warpN = wid >> 2;
    const int g = lane >> 2, t = lane & 3;

    extern __shared__ __half smh[];
    const uint32_t sbase = smem_u32(smh);

    const __half* aSrc[4]; uint32_t aDst[4];
    const __half* bSrc[4]; uint32_t bDst[4];
#pragma unroll
    for (int i = 0; i < 4; i++) {
        int c = tid + 256 * i;
        int row = c >> 3, col = c & 7;
        int r = m0 + row; if (r > nrows - 1) r = nrows - 1;
        aSrc[i] = g_hidh + (size_t)(off0 + r) * F_DIM + col * 8;
        aDst[i] = sbase + (row * PADH + col * 8) * 2;
        bSrc[i] = g_dwh + (size_t)e * H_DIM * F_DIM + (size_t)(n0 + row) * F_DIM + col * 8;
        bDst[i] = sbase + ((10240 + row * PADH + col * 8)) * 2;
    }

    float acc[2][8][4];
#pragma unroll
    for (int mt = 0; mt < 2; mt++)
#pragma unroll
        for (int nt = 0; nt < 8; nt++)
#pragma unroll
            for (int i = 0; i < 4; i++) acc[mt][nt][i] = 0.f;

#pragma unroll
    for (int i = 0; i < 4; i++) { cp16(aDst[i], aSrc[i]); cp16(bDst[i], bSrc[i]); }
    CP_COMMIT();

    const int NK = F_DIM / 64;  // 64
    for (int kb = 0; kb < NK; kb++) {
        const int s = kb & 1;
        if (kb + 1 < NK) {
            const uint32_t so = (uint32_t)((s ^ 1) * DN_STGH * 2);
            const int ko = (kb + 1) * 64;
#pragma unroll
            for (int i = 0; i < 4; i++) {
                cp16(aDst[i] + so, aSrc[i] + ko);
                cp16(bDst[i] + so, bSrc[i] + ko);
            }
            CP_COMMIT();
            CP_WAIT1();
        } else {
            CP_WAIT0();
        }
        __syncthreads();
        const __half* sA = smh + s * DN_STGH;
        const __half* sB = sA + 10240;
#pragma unroll
        for (int ks = 0; ks < 4; ks++) {
            const int k0 = ks * 16 + 4 * t;
            unsigned a[2][4], b[8][2];
#pragma unroll
            for (int mt = 0; mt < 2; mt++) {
                const int r0 = warpM * 32 + mt * 16 + g;
                uint2 v0 = *(const uint2*)(sA + r0 * PADH + k0);
                uint2 v1 = *(const uint2*)(sA + (r0 + 8) * PADH + k0);
                a[mt][0] = v0.x; a[mt][2] = v0.y;
                a[mt][1] = v1.x; a[mt][3] = v1.y;
            }
#pragma unroll
            for (int nt = 0; nt < 8; nt++) {
                const int rn = warpN * 64 + nt * 8 + g;
                uint2 vb = *(const uint2*)(sB + rn * PADH + k0);
                b[nt][0] = vb.x; b[nt][1] = vb.y;
            }
#pragma unroll
            for (int mt = 0; mt < 2; mt++)
#pragma unroll
                for (int nt = 0; nt < 8; nt++)
                    mma_f16(acc[mt][nt], a[mt], b[nt]);
        }
        __syncthreads();
    }

#pragma unroll
    for (int mt = 0; mt < 2; mt++) {
#pragma unroll
        for (int nt = 0; nt < 8; nt++) {
            const int col = n0 + warpN * 64 + nt * 8 + t * 2;
#pragma unroll
            for (int h = 0; h < 2; h++) {
                const int row = warpM * 32 + mt * 16 + g + h * 8;
                if (m0 + row < nrows) {
                    *(float2*)(g_dres + (size_t)(off0 + m0 + row) * H_DIM + col) =
                        make_float2(acc[mt][nt][h * 2 + 0], acc[mt][nt][h * 2 + 1]);
                }
            }
        }
    }
}

// ---------------- 5) combine ----------------
__global__ void combine_kernel(float* __restrict__ out) {
    int tt = blockIdx.x;
    int s0 = g_slot[2 * tt], s1 = g_slot[2 * tt + 1];
    const float4* p0 = (const float4*)(g_dres + (size_t)s0 * H_DIM);
    const float4* p1 = (const float4*)(g_dres + (size_t)s1 * H_DIM);
    float4* po = (float4*)(out + (size_t)tt * H_DIM);
    int i = threadIdx.x;
    float4 a = p0[i], b = p1[i];
    po[i] = make_float4(a.x + b.x, a.y + b.y, a.z + b.z, a.w + b.w);
}

// ---------------- launch ----------------
extern "C" void kernel_launch(void* const* d_in, const int* in_sizes, int n_in,
                              void* d_out, int out_size) {
    (void)in_sizes; (void)n_in; (void)out_size;
    const float* x  = (const float*)d_in[0];
    const float* rw = (const float*)d_in[1];
    const float* gw = (const float*)d_in[2];
    const float* uw = (const float*)d_in[3];
    const float* dw = (const float*)d_in[4];
    float* out = (float*)d_out;

    cudaFuncSetAttribute(gateup_mm, cudaFuncAttributeMaxDynamicSharedMemorySize, GU_SMEM);
    cudaFuncSetAttribute(down_mm,   cudaFuncAttributeMaxDynamicSharedMemorySize, DN_SMEM);

    __half* gwh; __half* uwh; __half* dwh;
    cudaGetSymbolAddress((void**)&gwh, g_gwh);
    cudaGetSymbolAddress((void**)&uwh, g_uwh);
    cudaGetSymbolAddress((void**)&dwh, g_dwh);

    const int n16 = WEL / 16;
    round_perm_kernel<<<dim3(2048, 3), 256>>>(gw, uw, dw, gwh, uwh, dwh, n16);

    router_kernel<<<T_TOKENS / 8, 256>>>(x, rw);
    build_kernel<<<1, 256>>>();
    gather_x_kernel<<<NPAIR / 4, 256>>>(x);

    gateup_mm<<<dim3(F_DIM / 64, NPAIR / 128, E_NUM), 256, GU_SMEM>>>(gwh, uwh);
    down_mm<<<dim3(H_DIM / 128, NPAIR / 128, E_NUM), 256, DN_SMEM>>>();
    combine_kernel<<<T_TOKENS, 256>>>(out);
}